// round 1
// baseline (speedup 1.0000x reference)
#include <cuda_runtime.h>
#include <cuda_bf16.h>
#include <math.h>

// Problem constants
#define BATCH 8
#define NPTS  2048
#define CDIM  128
#define PDIM  3
#define ODIM  256
#define KNN   16
#define ROWS  (BATCH * NPTS)       // 16384
#define KPAD  144                  // 131 padded up to multiple of 16
#define BN_EPS 1e-5f
#define INVN  (1.0f / (float)ROWS)

// ---------------- scratch (static device memory; no allocations) -------------
__device__ int   g_nn[ROWS * KNN];                 // 1 MB
__device__ float g_avg[ROWS * KPAD];               // 9.4 MB
__device__ float g_w1p[KPAD * ODIM];               // 147 KB (padded W1)
__device__ float g_c1[ROWS * ODIM];                // 16.8 MB (pre-BN layer1)
__device__ float g_h[ROWS * ODIM];                 // 16.8 MB (post BN+ReLU)
__device__ float g_part[2][128][2 * ODIM];         // per-block partial sum|sumsq
__device__ float g_stat[2][2 * ODIM];              // reduced sum|sumsq

// ---------------- prep: pad W1, nothing else needed ---------------------------
__global__ void prep_kernel(const float* __restrict__ W1) {
    int k = blockIdx.x;          // 0..143
    int o = threadIdx.x;         // 0..255
    g_w1p[k * ODIM + o] = (k < 131) ? W1[k * ODIM + o] : 0.0f;
}

// ---------------- KNN: thread per query, smem pos, top-16 in registers --------
__global__ void __launch_bounds__(256) knn_kernel(const float* __restrict__ pos) {
    __shared__ float4 sp[NPTS];                    // 32 KB
    int bb = blockIdx.x >> 3;                      // batch
    int r0 = (blockIdx.x & 7) << 8;                // query offset in batch
    const float* pb = pos + bb * NPTS * PDIM;
    for (int j = threadIdx.x; j < NPTS; j += 256) {
        sp[j] = make_float4(pb[j * 3 + 0], pb[j * 3 + 1], pb[j * 3 + 2], 0.0f);
    }
    __syncthreads();

    int i = r0 + threadIdx.x;
    float4 q = sp[i];

    float bd[KNN];
    int   bi[KNN];
#pragma unroll
    for (int k = 0; k < KNN; k++) { bd[k] = 3.402823466e38f; bi[k] = 0; }
    float wmax = 3.402823466e38f;
    int   wslot = 0;

    for (int j = 0; j < NPTS; j++) {
        float4 p = sp[j];
        float dx = q.x - p.x;
        float dy = q.y - p.y;
        float dz = q.z - p.z;
        float d = dx * dx + dy * dy + dz * dz;
        if (d < wmax) {                        // strict: ties keep earlier index (matches top_k)
            bd[wslot] = d;
            bi[wslot] = j;
            // rescan for new worst (argmax)
            float m = bd[0]; int s = 0;
#pragma unroll
            for (int k = 1; k < KNN; k++) {
                if (bd[k] > m) { m = bd[k]; s = k; }
            }
            wmax = m; wslot = s;
        }
    }
    int* o = g_nn + (bb * NPTS + i) * KNN;
#pragma unroll
    for (int k = 0; k < KNN; k++) o[k] = bi[k];
}

// ---------------- gather neighbors + mean -> avg[row][0..143] ----------------
__global__ void __launch_bounds__(128) gather_avg_kernel(const float* __restrict__ x,
                                                         const float* __restrict__ pos) {
    int row = blockIdx.x;                          // 0..16383
    int bb = row >> 11;
    __shared__ int sidx[KNN];
    if (threadIdx.x < KNN) sidx[threadIdx.x] = g_nn[row * KNN + threadIdx.x];
    __syncthreads();

    const float* xb = x + (size_t)bb * NPTS * CDIM;
    float s = 0.0f;
#pragma unroll
    for (int k = 0; k < KNN; k++) s += xb[sidx[k] * CDIM + threadIdx.x];
    g_avg[(size_t)row * KPAD + threadIdx.x] = s * (1.0f / (float)KNN);

    if (threadIdx.x < 16) {
        int c = threadIdx.x;
        float v = 0.0f;
        if (c < PDIM) {
            const float* pb = pos + bb * NPTS * PDIM;
#pragma unroll
            for (int k = 0; k < KNN; k++) v += pb[sidx[k] * PDIM + c];
            v *= (1.0f / (float)KNN);
        }
        g_avg[(size_t)row * KPAD + CDIM + c] = v;  // cols 128..130 pos-mean, 131..143 zero
    }
}

// ---------------- tiled fp32 GEMM: C[M x 256] = A[M x K(lda)] * B[K x 256] ----
// BM=128, BN=64, BK=16, 256 threads, 8x4 per-thread microtile.
__global__ void __launch_bounds__(256) gemm_kernel(const float* __restrict__ A, int lda, int K,
                                                   const float* __restrict__ B,
                                                   float* __restrict__ C) {
    __shared__ float As[16][132];   // transposed stage, padded
    __shared__ float Bs[16][68];

    int tid = threadIdx.x;
    int tx = tid & 15;              // col group (x4)
    int ty = tid >> 4;              // row group (x8)
    int mBase = blockIdx.y * 128;
    int nBase = blockIdx.x * 64;

    float acc[8][4];
#pragma unroll
    for (int i = 0; i < 8; i++)
#pragma unroll
        for (int j = 0; j < 4; j++) acc[i][j] = 0.0f;

    for (int k0 = 0; k0 < K; k0 += 16) {
#pragma unroll
        for (int it = 0; it < 2; it++) {
            int idx = tid + it * 256;            // 0..511 float4s of A tile
            int r = idx >> 2;
            int kq = (idx & 3) << 2;
            float4 v = *(const float4*)(A + (size_t)(mBase + r) * lda + k0 + kq);
            As[kq + 0][r] = v.x;
            As[kq + 1][r] = v.y;
            As[kq + 2][r] = v.z;
            As[kq + 3][r] = v.w;
        }
        {
            int kr = tid >> 4;
            int cq = (tid & 15) << 2;
            float4 v = *(const float4*)(B + (size_t)(k0 + kr) * ODIM + nBase + cq);
            *(float4*)&Bs[kr][cq] = v;
        }
        __syncthreads();
#pragma unroll
        for (int kk = 0; kk < 16; kk++) {
            float a[8], b[4];
            *(float4*)(a + 0) = *(float4*)&As[kk][ty * 8 + 0];
            *(float4*)(a + 4) = *(float4*)&As[kk][ty * 8 + 4];
            *(float4*)(b)     = *(float4*)&Bs[kk][tx * 4];
#pragma unroll
            for (int i = 0; i < 8; i++)
#pragma unroll
                for (int j = 0; j < 4; j++)
                    acc[i][j] = fmaf(a[i], b[j], acc[i][j]);
        }
        __syncthreads();
    }
#pragma unroll
    for (int i = 0; i < 8; i++) {
        float4 v = make_float4(acc[i][0], acc[i][1], acc[i][2], acc[i][3]);
        *(float4*)(C + (size_t)(mBase + ty * 8 + i) * ODIM + nBase + tx * 4) = v;
    }
}

// ---------------- BN stats: per-channel sum / sumsq (deterministic 2-stage) ---
__global__ void __launch_bounds__(256) stats_kernel(const float* __restrict__ Y, int layer) {
    int c = threadIdx.x;
    int r0 = blockIdx.x * 128;
    float s = 0.0f, q = 0.0f;
    for (int r = 0; r < 128; r++) {
        float v = Y[(size_t)(r0 + r) * ODIM + c];
        s += v;
        q = fmaf(v, v, q);
    }
    g_part[layer][blockIdx.x][c] = s;
    g_part[layer][blockIdx.x][ODIM + c] = q;
}

__global__ void __launch_bounds__(512) stats_reduce_kernel(int layer) {
    int t = threadIdx.x;                      // 0..511
    float s = 0.0f;
    for (int r = 0; r < 128; r++) s += g_part[layer][r][t];
    g_stat[layer][t] = s;
}

// ---------------- BN apply (+ optional ReLU), float4 elementwise --------------
__global__ void __launch_bounds__(256) bn_apply_kernel(const float* __restrict__ Y,
                                                       float* __restrict__ H,
                                                       int layer,
                                                       const float* __restrict__ gamma,
                                                       const float* __restrict__ beta,
                                                       int relu) {
    int idx = blockIdx.x * blockDim.x + threadIdx.x;   // one float4 each
    int e = idx * 4;
    int c = e & (ODIM - 1);
    float4 v = *(const float4*)(Y + e);
    float o[4] = {v.x, v.y, v.z, v.w};
#pragma unroll
    for (int j = 0; j < 4; j++) {
        int ch = c + j;
        float mu  = g_stat[layer][ch] * INVN;
        float var = fmaf(-mu, mu, g_stat[layer][ODIM + ch] * INVN);
        float sc = gamma[ch] * rsqrtf(var + BN_EPS);
        float r = fmaf(o[j] - mu, sc, beta[ch]);
        if (relu) r = fmaxf(r, 0.0f);
        o[j] = r;
    }
    *(float4*)(H + e) = make_float4(o[0], o[1], o[2], o[3]);
}

// ---------------- launcher ----------------------------------------------------
extern "C" void kernel_launch(void* const* d_in, const int* in_sizes, int n_in,
                              void* d_out, int out_size) {
    const float* x   = (const float*)d_in[0];   // [8,2048,128]
    const float* pos = (const float*)d_in[1];   // [8,2048,3]
    const float* W1  = (const float*)d_in[2];   // [131,256]
    // d_in[3] = b1 (cancels under train-mode BN)
    const float* g1  = (const float*)d_in[4];
    const float* be1 = (const float*)d_in[5];
    const float* W2  = (const float*)d_in[6];   // [256,256]
    // d_in[7] = b2 (cancels)
    const float* g2  = (const float*)d_in[8];
    const float* be2 = (const float*)d_in[9];
    float* out = (float*)d_out;                 // [8,2048,256]

    prep_kernel<<<KPAD, ODIM>>>(W1);
    knn_kernel<<<BATCH * (NPTS / 256), 256>>>(pos);
    gather_avg_kernel<<<ROWS, 128>>>(x, pos);

    float* avg = nullptr; float* w1p = nullptr; float* c1 = nullptr; float* h = nullptr;
    cudaGetSymbolAddress((void**)&avg, g_avg);
    cudaGetSymbolAddress((void**)&w1p, g_w1p);
    cudaGetSymbolAddress((void**)&c1,  g_c1);
    cudaGetSymbolAddress((void**)&h,   g_h);

    dim3 ggrid(ODIM / 64, ROWS / 128);
    gemm_kernel<<<ggrid, 256>>>(avg, KPAD, KPAD, w1p, c1);
    stats_kernel<<<128, 256>>>(c1, 0);
    stats_reduce_kernel<<<1, 512>>>(0);
    bn_apply_kernel<<<ROWS * ODIM / 4 / 256, 256>>>(c1, h, 0, g1, be1, 1);

    gemm_kernel<<<ggrid, 256>>>(h, ODIM, ODIM, W2, out);
    stats_kernel<<<128, 256>>>(out, 1);
    stats_reduce_kernel<<<1, 512>>>(1);
    bn_apply_kernel<<<ROWS * ODIM / 4 / 256, 256>>>(out, out, 1, g2, be2, 0);
}

// round 3
// speedup vs baseline: 1.4239x; 1.4239x over previous
#include <cuda_runtime.h>
#include <cuda_bf16.h>
#include <math.h>

// Problem constants
#define BATCH 8
#define NPTS  2048
#define CDIM  128
#define PDIM  3
#define ODIM  256
#define KNN   16
#define ROWS  (BATCH * NPTS)       // 16384
#define KPAD  144                  // 131 padded up to multiple of 16
#define BN_EPS 1e-5f
#define INVN  (1.0f / (float)ROWS)

typedef unsigned long long u64;

// ---------------- scratch (static device memory; no allocations) -------------
__device__ int   g_nn[ROWS * KNN];                 // 1 MB
__device__ float g_avg[ROWS * KPAD];               // 9.4 MB
__device__ float g_w1p[KPAD * ODIM];               // 147 KB (padded W1)
__device__ float g_c1[ROWS * ODIM];                // 16.8 MB (pre-BN layer1)
__device__ float g_part[2][128][2 * ODIM];         // per-block partial sum|sumsq
__device__ float g_scale[2][ODIM];                 // BN scale per layer
__device__ float g_shift[2][ODIM];                 // BN shift per layer

// ---------------- prep: pad W1 ------------------------------------------------
__global__ void prep_kernel(const float* __restrict__ W1) {
    int k = blockIdx.x;          // 0..143
    int o = threadIdx.x;         // 0..255
    g_w1p[k * ODIM + o] = (k < 131) ? W1[k * ODIM + o] : 0.0f;
}

// ---------------- KNN: thread per query, register-resident top-16 -------------
// State = 16 packed 64-bit keys: (float_bits(dist) << 32) | index.
// d >= 0 so float bits are order-monotonic; index in low bits makes every key
// UNIQUE and reproduces jax.lax.top_k tie semantics (earlier index wins).
// Unique keys -> equality-eviction of the max key touches exactly one slot,
// all array indices static -> fully register resident.
__device__ __forceinline__ u64 umax64(u64 a, u64 b) { return a > b ? a : b; }

__device__ __forceinline__ void insert16(u64 (&bk)[KNN], u64& wmax, u64 key) {
#pragma unroll
    for (int k = 0; k < KNN; k++) {
        if (bk[k] == wmax) bk[k] = key;      // unique match: exactly one slot
    }
    u64 m0 = umax64(bk[0], bk[1]),   m1 = umax64(bk[2], bk[3]);
    u64 m2 = umax64(bk[4], bk[5]),   m3 = umax64(bk[6], bk[7]);
    u64 m4 = umax64(bk[8], bk[9]),   m5 = umax64(bk[10], bk[11]);
    u64 m6 = umax64(bk[12], bk[13]), m7 = umax64(bk[14], bk[15]);
    m0 = umax64(m0, m1); m2 = umax64(m2, m3);
    m4 = umax64(m4, m5); m6 = umax64(m6, m7);
    m0 = umax64(m0, m2); m4 = umax64(m4, m6);
    wmax = umax64(m0, m4);
}

__global__ void __launch_bounds__(64) knn_kernel(const float* __restrict__ pos) {
    __shared__ float4 sp[NPTS];                    // 32 KB
    int bb = blockIdx.x >> 5;                      // batch (32 blocks per batch)
    int r0 = (blockIdx.x & 31) << 6;               // query offset in batch
    const float* pb = pos + bb * NPTS * PDIM;
    for (int j = threadIdx.x; j < NPTS; j += 64) {
        sp[j] = make_float4(pb[j * 3 + 0], pb[j * 3 + 1], pb[j * 3 + 2], 0.0f);
    }
    __syncthreads();

    int i = r0 + threadIdx.x;
    float4 q = sp[i];

    u64 bk[KNN];
#pragma unroll
    for (int k = 0; k < KNN; k++) bk[k] = 0xFFF0000000000000ull + (u64)k; // > any real key
    u64 wmax = 0xFFF000000000000Full;

    for (int j = 0; j < NPTS; j += 2) {
        float4 p0 = sp[j];
        float4 p1 = sp[j + 1];
        float dx0 = q.x - p0.x, dy0 = q.y - p0.y, dz0 = q.z - p0.z;
        float dx1 = q.x - p1.x, dy1 = q.y - p1.y, dz1 = q.z - p1.z;
        float d0 = dx0 * dx0 + dy0 * dy0 + dz0 * dz0;
        float d1 = dx1 * dx1 + dy1 * dy1 + dz1 * dz1;
        u64 k0 = ((u64)__float_as_uint(d0) << 32) | (unsigned)j;
        u64 k1 = ((u64)__float_as_uint(d1) << 32) | (unsigned)(j + 1);
        if (k0 < wmax) insert16(bk, wmax, k0);
        if (k1 < wmax) insert16(bk, wmax, k1);
    }
    int* o = g_nn + (bb * NPTS + i) * KNN;
#pragma unroll
    for (int k = 0; k < KNN; k++) o[k] = (int)(bk[k] & 0xFFFFFFFFu);
}

// ---------------- gather neighbors + mean -> avg[row][0..143] ----------------
__global__ void __launch_bounds__(128) gather_avg_kernel(const float* __restrict__ x,
                                                         const float* __restrict__ pos) {
    int row = blockIdx.x;                          // 0..16383
    int bb = row >> 11;
    __shared__ int sidx[KNN];
    if (threadIdx.x < KNN) sidx[threadIdx.x] = g_nn[row * KNN + threadIdx.x];
    __syncthreads();

    const float* xb = x + (size_t)bb * NPTS * CDIM;
    float s = 0.0f;
#pragma unroll
    for (int k = 0; k < KNN; k++) s += xb[sidx[k] * CDIM + threadIdx.x];
    g_avg[(size_t)row * KPAD + threadIdx.x] = s * (1.0f / (float)KNN);

    if (threadIdx.x < 16) {
        int c = threadIdx.x;
        float v = 0.0f;
        if (c < PDIM) {
            const float* pb = pos + bb * NPTS * PDIM;
#pragma unroll
            for (int k = 0; k < KNN; k++) v += pb[sidx[k] * PDIM + c];
            v *= (1.0f / (float)KNN);
        }
        g_avg[(size_t)row * KPAD + CDIM + c] = v;  // cols 128..130 pos-mean, rest 0
    }
}

// ---------------- tiled fp32 GEMM: C[M x 256] = op(A)[M x K(lda)] * B[K x 256]
// BM=128, BN=64, BK=16, 256 threads, 8x4 microtile.
// FUSE: apply y = relu(a*scale[k] + shift[k]) to A elements while staging
// (folds BN1+ReLU of layer 1 into the layer-2 GEMM).
template <bool FUSE>
__global__ void __launch_bounds__(256) gemm_kernel(const float* __restrict__ A, int lda, int K,
                                                   const float* __restrict__ B,
                                                   float* __restrict__ C) {
    __shared__ float As[16][132];   // transposed stage, padded
    __shared__ float Bs[16][68];
    __shared__ float s_sc[ODIM];
    __shared__ float s_sh[ODIM];

    int tid = threadIdx.x;
    if (FUSE) {
        s_sc[tid] = g_scale[0][tid];
        s_sh[tid] = g_shift[0][tid];
    }
    int tx = tid & 15;              // col group (x4)
    int ty = tid >> 4;              // row group (x8)
    int mBase = blockIdx.y * 128;
    int nBase = blockIdx.x * 64;
    if (FUSE) __syncthreads();

    float acc[8][4];
#pragma unroll
    for (int i = 0; i < 8; i++)
#pragma unroll
        for (int j = 0; j < 4; j++) acc[i][j] = 0.0f;

    for (int k0 = 0; k0 < K; k0 += 16) {
#pragma unroll
        for (int it = 0; it < 2; it++) {
            int idx = tid + it * 256;            // 0..511 float4s of A tile
            int r = idx >> 2;
            int kq = (idx & 3) << 2;
            float4 v = *(const float4*)(A + (size_t)(mBase + r) * lda + k0 + kq);
            if (FUSE) {
                v.x = fmaxf(fmaf(v.x, s_sc[k0 + kq + 0], s_sh[k0 + kq + 0]), 0.0f);
                v.y = fmaxf(fmaf(v.y, s_sc[k0 + kq + 1], s_sh[k0 + kq + 1]), 0.0f);
                v.z = fmaxf(fmaf(v.z, s_sc[k0 + kq + 2], s_sh[k0 + kq + 2]), 0.0f);
                v.w = fmaxf(fmaf(v.w, s_sc[k0 + kq + 3], s_sh[k0 + kq + 3]), 0.0f);
            }
            As[kq + 0][r] = v.x;
            As[kq + 1][r] = v.y;
            As[kq + 2][r] = v.z;
            As[kq + 3][r] = v.w;
        }
        {
            int kr = tid >> 4;
            int cq = (tid & 15) << 2;
            float4 v = *(const float4*)(B + (size_t)(k0 + kr) * ODIM + nBase + cq);
            *(float4*)&Bs[kr][cq] = v;
        }
        __syncthreads();
#pragma unroll
        for (int kk = 0; kk < 16; kk++) {
            float a[8], b[4];
            *(float4*)(a + 0) = *(float4*)&As[kk][ty * 8 + 0];
            *(float4*)(a + 4) = *(float4*)&As[kk][ty * 8 + 4];
            *(float4*)(b)     = *(float4*)&Bs[kk][tx * 4];
#pragma unroll
            for (int i = 0; i < 8; i++)
#pragma unroll
                for (int j = 0; j < 4; j++)
                    acc[i][j] = fmaf(a[i], b[j], acc[i][j]);
        }
        __syncthreads();
    }
#pragma unroll
    for (int i = 0; i < 8; i++) {
        float4 v = make_float4(acc[i][0], acc[i][1], acc[i][2], acc[i][3]);
        *(float4*)(C + (size_t)(mBase + ty * 8 + i) * ODIM + nBase + tx * 4) = v;
    }
}

// ---------------- BN stats: per-channel sum / sumsq (deterministic 2-stage) ---
__global__ void __launch_bounds__(256) stats_kernel(const float* __restrict__ Y, int layer) {
    int c = threadIdx.x;
    int r0 = blockIdx.x * 128;
    float s = 0.0f, q = 0.0f;
    for (int r = 0; r < 128; r++) {
        float v = Y[(size_t)(r0 + r) * ODIM + c];
        s += v;
        q = fmaf(v, v, q);
    }
    g_part[layer][blockIdx.x][c] = s;
    g_part[layer][blockIdx.x][ODIM + c] = q;
}

// reduce partials + compute per-channel scale/shift
__global__ void __launch_bounds__(512) stats_reduce_kernel(int layer,
                                                           const float* __restrict__ gamma,
                                                           const float* __restrict__ beta) {
    __shared__ float ssum[2 * ODIM];
    int t = threadIdx.x;                      // 0..511
    float s = 0.0f;
    for (int r = 0; r < 128; r++) s += g_part[layer][r][t];
    ssum[t] = s;
    __syncthreads();
    if (t < ODIM) {
        float mu  = ssum[t] * INVN;
        float var = fmaf(-mu, mu, ssum[ODIM + t] * INVN);
        float sc = gamma[t] * rsqrtf(var + BN_EPS);
        g_scale[layer][t] = sc;
        g_shift[layer][t] = fmaf(-mu, sc, beta[t]);
    }
}

// ---------------- BN apply (final layer, no ReLU), float4 elementwise ---------
__global__ void __launch_bounds__(256) bn_apply_kernel(float* __restrict__ Y, int layer) {
    int idx = blockIdx.x * blockDim.x + threadIdx.x;   // one float4 each
    int e = idx * 4;
    int c = e & (ODIM - 1);
    float4 v = *(const float4*)(Y + e);
    float o[4] = {v.x, v.y, v.z, v.w};
#pragma unroll
    for (int j = 0; j < 4; j++) {
        int ch = c + j;
        o[j] = fmaf(o[j], g_scale[layer][ch], g_shift[layer][ch]);
    }
    *(float4*)(Y + e) = make_float4(o[0], o[1], o[2], o[3]);
}

// ---------------- launcher ----------------------------------------------------
extern "C" void kernel_launch(void* const* d_in, const int* in_sizes, int n_in,
                              void* d_out, int out_size) {
    const float* x   = (const float*)d_in[0];   // [8,2048,128]
    const float* pos = (const float*)d_in[1];   // [8,2048,3]
    const float* W1  = (const float*)d_in[2];   // [131,256]
    // d_in[3] = b1 (cancels under train-mode BN)
    const float* g1  = (const float*)d_in[4];
    const float* be1 = (const float*)d_in[5];
    const float* W2  = (const float*)d_in[6];   // [256,256]
    // d_in[7] = b2 (cancels)
    const float* g2  = (const float*)d_in[8];
    const float* be2 = (const float*)d_in[9];
    float* out = (float*)d_out;                 // [8,2048,256]

    prep_kernel<<<KPAD, ODIM>>>(W1);
    knn_kernel<<<BATCH * (NPTS / 64), 64>>>(pos);
    gather_avg_kernel<<<ROWS, 128>>>(x, pos);

    float* avg = nullptr; float* w1p = nullptr; float* c1 = nullptr;
    cudaGetSymbolAddress((void**)&avg, g_avg);
    cudaGetSymbolAddress((void**)&w1p, g_w1p);
    cudaGetSymbolAddress((void**)&c1,  g_c1);

    dim3 ggrid(ODIM / 64, ROWS / 128);
    gemm_kernel<false><<<ggrid, 256>>>(avg, KPAD, KPAD, w1p, c1);
    stats_kernel<<<128, 256>>>(c1, 0);
    stats_reduce_kernel<<<1, 512>>>(0, g1, be1);

    // layer-2 GEMM with BN1+ReLU fused into A staging
    gemm_kernel<true><<<ggrid, 256>>>(c1, ODIM, ODIM, W2, out);
    stats_kernel<<<128, 256>>>(out, 1);
    stats_reduce_kernel<<<1, 512>>>(1, g2, be2);
    bn_apply_kernel<<<ROWS * ODIM / 4 / 256, 256>>>(out, 1);
}

// round 4
// speedup vs baseline: 1.8648x; 1.3096x over previous
#include <cuda_runtime.h>
#include <cuda_bf16.h>
#include <math.h>

// Problem constants
#define BATCH 8
#define NPTS  2048
#define CDIM  128
#define PDIM  3
#define ODIM  256
#define KNN   16
#define ROWS  (BATCH * NPTS)       // 16384
#define KPAD  144                  // 131 padded up to multiple of 16
#define BN_EPS 1e-5f
#define INVN  (1.0f / (float)ROWS)

typedef unsigned long long u64;

// ---------------- scratch (static device memory; no allocations) -------------
__device__ int   g_nn[ROWS * KNN];                 // 1 MB
__device__ float g_avg[ROWS * KPAD];               // 9.4 MB
__device__ float g_w1p[KPAD * ODIM];               // 147 KB (padded W1)
__device__ float g_c1[ROWS * ODIM];                // 16.8 MB (pre-BN layer1)
__device__ float g_part[2][128][2 * ODIM];         // per-block partial sum|sumsq
__device__ float g_scale[2][ODIM];                 // BN scale per layer
__device__ float g_shift[2][ODIM];                 // BN shift per layer

// ---------------- prep: pad W1 ------------------------------------------------
__global__ void prep_kernel(const float* __restrict__ W1) {
    int k = blockIdx.x;          // 0..143
    int o = threadIdx.x;         // 0..255
    g_w1p[k * ODIM + o] = (k < 131) ? W1[k * ODIM + o] : 0.0f;
}

// ---------------- KNN --------------------------------------------------------
// Thread per query; candidates gated by (key < wmax) are PUSHED to a per-lane
// shared-memory buffer (predicated STS, no divergence). A flush processes the
// buffers in lockstep: round k inserts the k-th buffered candidate of EVERY
// lane in one warp-wide insert16 execution, so the expensive maintain path is
// paid O(max-lane-inserts) times instead of O(any-lane-insert events).
// Keys are unique u64 (dist_bits<<32 | index): exact jax.lax.top_k semantics.
__device__ __forceinline__ u64 umax64(u64 a, u64 b) { return a > b ? a : b; }

__device__ __forceinline__ void insert16(u64 (&bk)[KNN], u64& wmax, u64 key) {
#pragma unroll
    for (int k = 0; k < KNN; k++) {
        if (bk[k] == wmax) bk[k] = key;      // unique keys: exactly one slot
    }
    u64 m0 = umax64(bk[0], bk[1]),   m1 = umax64(bk[2], bk[3]);
    u64 m2 = umax64(bk[4], bk[5]),   m3 = umax64(bk[6], bk[7]);
    u64 m4 = umax64(bk[8], bk[9]),   m5 = umax64(bk[10], bk[11]);
    u64 m6 = umax64(bk[12], bk[13]), m7 = umax64(bk[14], bk[15]);
    m0 = umax64(m0, m1); m2 = umax64(m2, m3);
    m4 = umax64(m4, m5); m6 = umax64(m6, m7);
    m0 = umax64(m0, m2); m4 = umax64(m4, m6);
    wmax = umax64(m0, m4);
}

__device__ __forceinline__ int warp_max_i(int v) {
    v = max(v, __shfl_xor_sync(0xFFFFFFFFu, v, 16));
    v = max(v, __shfl_xor_sync(0xFFFFFFFFu, v, 8));
    v = max(v, __shfl_xor_sync(0xFFFFFFFFu, v, 4));
    v = max(v, __shfl_xor_sync(0xFFFFFFFFu, v, 2));
    v = max(v, __shfl_xor_sync(0xFFFFFFFFu, v, 1));
    return v;
}

__global__ void __launch_bounds__(64) knn_kernel(const float* __restrict__ pos) {
    __shared__ float4 sp[NPTS];                    // 32 KB
    __shared__ u64 sbuf[64 * 16];                  // 8 KB deferred-candidate buffers
    int tid = threadIdx.x;
    int bb = blockIdx.x >> 5;                      // batch (32 blocks per batch)
    int r0 = (blockIdx.x & 31) << 6;               // query offset in batch
    const float* pb = pos + bb * NPTS * PDIM;
    for (int j = tid; j < NPTS; j += 64) {
        sp[j] = make_float4(pb[j * 3 + 0], pb[j * 3 + 1], pb[j * 3 + 2], 0.0f);
    }
    __syncthreads();

    int i = r0 + tid;
    float4 q = sp[i];

    u64 bk[KNN];
#pragma unroll
    for (int k = 0; k < KNN; k++) bk[k] = 0xFFF0000000000000ull + (u64)k; // > any real key
    u64 wmax = 0xFFF000000000000Full;

    int n = 0;                    // buffered candidate count
    int base = tid * 16;

    for (int j0 = 0; j0 < NPTS; j0 += 8) {
#pragma unroll
        for (int c = 0; c < 8; c++) {
            float4 p = sp[j0 + c];
            float dx = q.x - p.x, dy = q.y - p.y, dz = q.z - p.z;
            float d = dx * dx + dy * dy + dz * dz;
            u64 key = ((u64)__float_as_uint(d) << 32) | (unsigned)(j0 + c);
            if (key < wmax) {                 // predicated push, no divergence
                sbuf[base + n] = key;
                n++;
            }
        }
        if (__any_sync(0xFFFFFFFFu, n >= 8)) {
            int mx = warp_max_i(n);
            for (int k = 0; k < mx; k++) {    // lockstep rounds: 1 insert per lane per round
                u64 key = sbuf[base + k];
                if (k < n && key < wmax) {    // re-gate: wmax tightens during flush
                    insert16(bk, wmax, key);
                }
            }
            n = 0;
        }
    }
    {   // final flush
        int mx = warp_max_i(n);
        for (int k = 0; k < mx; k++) {
            u64 key = sbuf[base + k];
            if (k < n && key < wmax) insert16(bk, wmax, key);
        }
    }

    int* o = g_nn + (bb * NPTS + i) * KNN;
#pragma unroll
    for (int k = 0; k < KNN; k++) o[k] = (int)(bk[k] & 0xFFFFFFFFu);
}

// ---------------- gather neighbors + mean -> avg[row][0..143] ----------------
__global__ void __launch_bounds__(128) gather_avg_kernel(const float* __restrict__ x,
                                                         const float* __restrict__ pos) {
    int row = blockIdx.x;                          // 0..16383
    int bb = row >> 11;
    __shared__ int sidx[KNN];
    if (threadIdx.x < KNN) sidx[threadIdx.x] = g_nn[row * KNN + threadIdx.x];
    __syncthreads();

    const float* xb = x + (size_t)bb * NPTS * CDIM;
    float s = 0.0f;
#pragma unroll
    for (int k = 0; k < KNN; k++) s += xb[sidx[k] * CDIM + threadIdx.x];
    g_avg[(size_t)row * KPAD + threadIdx.x] = s * (1.0f / (float)KNN);

    if (threadIdx.x < 16) {
        int c = threadIdx.x;
        float v = 0.0f;
        if (c < PDIM) {
            const float* pb = pos + bb * NPTS * PDIM;
#pragma unroll
            for (int k = 0; k < KNN; k++) v += pb[sidx[k] * PDIM + c];
            v *= (1.0f / (float)KNN);
        }
        g_avg[(size_t)row * KPAD + CDIM + c] = v;  // cols 128..130 pos-mean, rest 0
    }
}

// ---------------- tiled fp32 GEMM: C[M x 256] = op(A)[M x K(lda)] * B[K x 256]
// BM=128, BN=64, BK=16, 256 threads, 8x4 microtile.
// FUSE: apply y = relu(a*scale[k] + shift[k]) to A elements while staging.
template <bool FUSE>
__global__ void __launch_bounds__(256) gemm_kernel(const float* __restrict__ A, int lda, int K,
                                                   const float* __restrict__ B,
                                                   float* __restrict__ C) {
    __shared__ float As[16][132];   // transposed stage, padded
    __shared__ float Bs[16][68];
    __shared__ float s_sc[ODIM];
    __shared__ float s_sh[ODIM];

    int tid = threadIdx.x;
    if (FUSE) {
        s_sc[tid] = g_scale[0][tid];
        s_sh[tid] = g_shift[0][tid];
    }
    int tx = tid & 15;              // col group (x4)
    int ty = tid >> 4;              // row group (x8)
    int mBase = blockIdx.y * 128;
    int nBase = blockIdx.x * 64;
    if (FUSE) __syncthreads();

    float acc[8][4];
#pragma unroll
    for (int i = 0; i < 8; i++)
#pragma unroll
        for (int j = 0; j < 4; j++) acc[i][j] = 0.0f;

    for (int k0 = 0; k0 < K; k0 += 16) {
#pragma unroll
        for (int it = 0; it < 2; it++) {
            int idx = tid + it * 256;            // 0..511 float4s of A tile
            int r = idx >> 2;
            int kq = (idx & 3) << 2;
            float4 v = *(const float4*)(A + (size_t)(mBase + r) * lda + k0 + kq);
            if (FUSE) {
                v.x = fmaxf(fmaf(v.x, s_sc[k0 + kq + 0], s_sh[k0 + kq + 0]), 0.0f);
                v.y = fmaxf(fmaf(v.y, s_sc[k0 + kq + 1], s_sh[k0 + kq + 1]), 0.0f);
                v.z = fmaxf(fmaf(v.z, s_sc[k0 + kq + 2], s_sh[k0 + kq + 2]), 0.0f);
                v.w = fmaxf(fmaf(v.w, s_sc[k0 + kq + 3], s_sh[k0 + kq + 3]), 0.0f);
            }
            As[kq + 0][r] = v.x;
            As[kq + 1][r] = v.y;
            As[kq + 2][r] = v.z;
            As[kq + 3][r] = v.w;
        }
        {
            int kr = tid >> 4;
            int cq = (tid & 15) << 2;
            float4 v = *(const float4*)(B + (size_t)(k0 + kr) * ODIM + nBase + cq);
            *(float4*)&Bs[kr][cq] = v;
        }
        __syncthreads();
#pragma unroll
        for (int kk = 0; kk < 16; kk++) {
            float a[8], b[4];
            *(float4*)(a + 0) = *(float4*)&As[kk][ty * 8 + 0];
            *(float4*)(a + 4) = *(float4*)&As[kk][ty * 8 + 4];
            *(float4*)(b)     = *(float4*)&Bs[kk][tx * 4];
#pragma unroll
            for (int i = 0; i < 8; i++)
#pragma unroll
                for (int j = 0; j < 4; j++)
                    acc[i][j] = fmaf(a[i], b[j], acc[i][j]);
        }
        __syncthreads();
    }
#pragma unroll
    for (int i = 0; i < 8; i++) {
        float4 v = make_float4(acc[i][0], acc[i][1], acc[i][2], acc[i][3]);
        *(float4*)(C + (size_t)(mBase + ty * 8 + i) * ODIM + nBase + tx * 4) = v;
    }
}

// ---------------- BN stats: per-channel sum / sumsq (deterministic 2-stage) ---
__global__ void __launch_bounds__(256) stats_kernel(const float* __restrict__ Y, int layer) {
    int c = threadIdx.x;
    int r0 = blockIdx.x * 128;
    float s = 0.0f, q = 0.0f;
    for (int r = 0; r < 128; r++) {
        float v = Y[(size_t)(r0 + r) * ODIM + c];
        s += v;
        q = fmaf(v, v, q);
    }
    g_part[layer][blockIdx.x][c] = s;
    g_part[layer][blockIdx.x][ODIM + c] = q;
}

// reduce partials + compute per-channel scale/shift
__global__ void __launch_bounds__(512) stats_reduce_kernel(int layer,
                                                           const float* __restrict__ gamma,
                                                           const float* __restrict__ beta) {
    __shared__ float ssum[2 * ODIM];
    int t = threadIdx.x;                      // 0..511
    float s = 0.0f;
    for (int r = 0; r < 128; r++) s += g_part[layer][r][t];
    ssum[t] = s;
    __syncthreads();
    if (t < ODIM) {
        float mu  = ssum[t] * INVN;
        float var = fmaf(-mu, mu, ssum[ODIM + t] * INVN);
        float sc = gamma[t] * rsqrtf(var + BN_EPS);
        g_scale[layer][t] = sc;
        g_shift[layer][t] = fmaf(-mu, sc, beta[t]);
    }
}

// ---------------- BN apply (final layer, no ReLU), float4 elementwise ---------
__global__ void __launch_bounds__(256) bn_apply_kernel(float* __restrict__ Y, int layer) {
    int idx = blockIdx.x * blockDim.x + threadIdx.x;   // one float4 each
    int e = idx * 4;
    int c = e & (ODIM - 1);
    float4 v = *(const float4*)(Y + e);
    float o[4] = {v.x, v.y, v.z, v.w};
#pragma unroll
    for (int j = 0; j < 4; j++) {
        int ch = c + j;
        o[j] = fmaf(o[j], g_scale[layer][ch], g_shift[layer][ch]);
    }
    *(float4*)(Y + e) = make_float4(o[0], o[1], o[2], o[3]);
}

// ---------------- launcher ----------------------------------------------------
extern "C" void kernel_launch(void* const* d_in, const int* in_sizes, int n_in,
                              void* d_out, int out_size) {
    const float* x   = (const float*)d_in[0];   // [8,2048,128]
    const float* pos = (const float*)d_in[1];   // [8,2048,3]
    const float* W1  = (const float*)d_in[2];   // [131,256]
    // d_in[3] = b1 (cancels under train-mode BN)
    const float* g1  = (const float*)d_in[4];
    const float* be1 = (const float*)d_in[5];
    const float* W2  = (const float*)d_in[6];   // [256,256]
    // d_in[7] = b2 (cancels)
    const float* g2  = (const float*)d_in[8];
    const float* be2 = (const float*)d_in[9];
    float* out = (float*)d_out;                 // [8,2048,256]

    prep_kernel<<<KPAD, ODIM>>>(W1);
    knn_kernel<<<BATCH * (NPTS / 64), 64>>>(pos);
    gather_avg_kernel<<<ROWS, 128>>>(x, pos);

    float* avg = nullptr; float* w1p = nullptr; float* c1 = nullptr;
    cudaGetSymbolAddress((void**)&avg, g_avg);
    cudaGetSymbolAddress((void**)&w1p, g_w1p);
    cudaGetSymbolAddress((void**)&c1,  g_c1);

    dim3 ggrid(ODIM / 64, ROWS / 128);
    gemm_kernel<false><<<ggrid, 256>>>(avg, KPAD, KPAD, w1p, c1);
    stats_kernel<<<128, 256>>>(c1, 0);
    stats_reduce_kernel<<<1, 512>>>(0, g1, be1);

    // layer-2 GEMM with BN1+ReLU fused into A staging
    gemm_kernel<true><<<ggrid, 256>>>(c1, ODIM, ODIM, W2, out);
    stats_kernel<<<128, 256>>>(out, 1);
    stats_reduce_kernel<<<1, 512>>>(1, g2, be2);
    bn_apply_kernel<<<ROWS * ODIM / 4 / 256, 256>>>(out, 1);
}

// round 5
// speedup vs baseline: 2.1830x; 1.1707x over previous
#include <cuda_runtime.h>
#include <cuda_bf16.h>
#include <math.h>

// Problem constants
#define BATCH 8
#define NPTS  2048
#define CDIM  128
#define PDIM  3
#define ODIM  256
#define KNN   16
#define ROWS  (BATCH * NPTS)       // 16384
#define KPAD  144                  // 131 padded up to multiple of 16
#define BN_EPS 1e-5f
#define INVN  (1.0f / (float)ROWS)
#define SBLK  256                  // stats blocks
#define SROWS (ROWS / SBLK)        // 64 rows per stats block

typedef unsigned long long u64;

// ---------------- scratch (static device memory; no allocations) -------------
__device__ int   g_nn[ROWS * KNN];                 // 1 MB
__device__ float g_avg[ROWS * KPAD];               // 9.4 MB
__device__ float g_w1p[KPAD * ODIM];               // 147 KB (padded W1)
__device__ float g_c1[ROWS * ODIM];                // 16.8 MB (pre-BN layer1)
__device__ float g_part[2][SBLK][2 * ODIM];        // per-block partial sum|sumsq
__device__ float g_scale[2][ODIM];                 // BN scale per layer
__device__ float g_shift[2][ODIM];                 // BN shift per layer

// ---------------- prep: pad W1 ------------------------------------------------
__global__ void prep_kernel(const float* __restrict__ W1) {
    int k = blockIdx.x;          // 0..143
    int o = threadIdx.x;         // 0..255
    g_w1p[k * ODIM + o] = (k < 131) ? W1[k * ODIM + o] : 0.0f;
}

// ---------------- KNN --------------------------------------------------------
// 2 threads per query (even/odd point parity). Each maintains a register
// top-16 of its half via deferred batched inserts (per-lane smem buffer,
// transposed layout for conflict-free access). Final pair-merge via shfl:
// union of half-top16s contains the true top16; unique u64 keys
// (dist_bits<<32 | idx) make selection exactly jax.lax.top_k semantics.
__device__ __forceinline__ u64 umax64(u64 a, u64 b) { return a > b ? a : b; }

__device__ __forceinline__ void insert16(u64 (&bk)[KNN], u64& wmax, u64 key) {
#pragma unroll
    for (int k = 0; k < KNN; k++) {
        if (bk[k] == wmax) bk[k] = key;      // unique keys: exactly one slot
    }
    u64 m0 = umax64(bk[0], bk[1]),   m1 = umax64(bk[2], bk[3]);
    u64 m2 = umax64(bk[4], bk[5]),   m3 = umax64(bk[6], bk[7]);
    u64 m4 = umax64(bk[8], bk[9]),   m5 = umax64(bk[10], bk[11]);
    u64 m6 = umax64(bk[12], bk[13]), m7 = umax64(bk[14], bk[15]);
    m0 = umax64(m0, m1); m2 = umax64(m2, m3);
    m4 = umax64(m4, m5); m6 = umax64(m6, m7);
    m0 = umax64(m0, m2); m4 = umax64(m4, m6);
    wmax = umax64(m0, m4);
}

__device__ __forceinline__ int warp_max_i(int v) {
    v = max(v, __shfl_xor_sync(0xFFFFFFFFu, v, 16));
    v = max(v, __shfl_xor_sync(0xFFFFFFFFu, v, 8));
    v = max(v, __shfl_xor_sync(0xFFFFFFFFu, v, 4));
    v = max(v, __shfl_xor_sync(0xFFFFFFFFu, v, 2));
    v = max(v, __shfl_xor_sync(0xFFFFFFFFu, v, 1));
    return v;
}

__global__ void __launch_bounds__(128) knn_kernel(const float* __restrict__ pos) {
    __shared__ float4 sp[NPTS];                    // 32 KB
    __shared__ u64 sbuf[16][128];                  // 16 KB, [slot][lane]: 2-way max
    int tid = threadIdx.x;
    int bb = blockIdx.x >> 5;                      // batch (32 blocks per batch)
    int r0 = (blockIdx.x & 31) << 6;               // query offset in batch (64/block)
    const float* pb = pos + bb * NPTS * PDIM;
    for (int j = tid; j < NPTS; j += 128) {
        sp[j] = make_float4(pb[j * 3 + 0], pb[j * 3 + 1], pb[j * 3 + 2], 0.0f);
    }
    __syncthreads();

    int qi = r0 + (tid >> 1);                      // query index (pairs share)
    int sub = tid & 1;                             // parity of points scanned
    float4 q = sp[qi];

    u64 bk[KNN];
#pragma unroll
    for (int k = 0; k < KNN; k++) bk[k] = 0xFFF0000000000000ull + (u64)k; // > any real key
    u64 wmax = 0xFFF000000000000Full;

    int n = 0;                    // buffered candidate count (<=15 guaranteed)

    for (int j0 = 0; j0 < NPTS; j0 += 16) {
#pragma unroll
        for (int c = 0; c < 8; c++) {
            int j = j0 + 2 * c + sub;
            float4 p = sp[j];
            float dx = q.x - p.x, dy = q.y - p.y, dz = q.z - p.z;
            float d = dx * dx + dy * dy + dz * dz;
            u64 key = ((u64)__float_as_uint(d) << 32) | (unsigned)j;
            if (key < wmax) {                 // predicated push, no divergence
                sbuf[n][tid] = key;
                n++;
            }
        }
        if (__any_sync(0xFFFFFFFFu, n >= 8)) {
            int mx = warp_max_i(n);
            for (int k = 0; k < mx; k++) {    // lockstep rounds
                u64 key = sbuf[k][tid];
                if (k < n && key < wmax) {    // re-gate: wmax tightens during flush
                    insert16(bk, wmax, key);
                }
            }
            n = 0;
        }
    }
    {   // final flush
        int mx = warp_max_i(n);
        for (int k = 0; k < mx; k++) {
            u64 key = sbuf[k][tid];
            if (k < n && key < wmax) insert16(bk, wmax, key);
        }
    }

    // pair merge: even lane absorbs odd lane's 16 keys (exact: union superset)
#pragma unroll
    for (int k = 0; k < KNN; k++) {
        u64 pk = __shfl_xor_sync(0xFFFFFFFFu, bk[k], 1);
        if (sub == 0 && pk < wmax) insert16(bk, wmax, pk);
    }

    if (sub == 0) {
        int* o = g_nn + (bb * NPTS + qi) * KNN;
#pragma unroll
        for (int k = 0; k < KNN; k++) o[k] = (int)(bk[k] & 0xFFFFFFFFu);
    }
}

// ---------------- gather neighbors + mean -> avg[row][0..143] ----------------
__global__ void __launch_bounds__(128) gather_avg_kernel(const float* __restrict__ x,
                                                         const float* __restrict__ pos) {
    int row = blockIdx.x;                          // 0..16383
    int bb = row >> 11;
    __shared__ int sidx[KNN];
    if (threadIdx.x < KNN) sidx[threadIdx.x] = g_nn[row * KNN + threadIdx.x];
    __syncthreads();

    const float* xb = x + (size_t)bb * NPTS * CDIM;
    float s = 0.0f;
#pragma unroll
    for (int k = 0; k < KNN; k++) s += xb[sidx[k] * CDIM + threadIdx.x];
    g_avg[(size_t)row * KPAD + threadIdx.x] = s * (1.0f / (float)KNN);

    if (threadIdx.x < 16) {
        int c = threadIdx.x;
        float v = 0.0f;
        if (c < PDIM) {
            const float* pb = pos + bb * NPTS * PDIM;
#pragma unroll
            for (int k = 0; k < KNN; k++) v += pb[sidx[k] * PDIM + c];
            v *= (1.0f / (float)KNN);
        }
        g_avg[(size_t)row * KPAD + CDIM + c] = v;  // cols 128..130 pos-mean, rest 0
    }
}

// ---------------- tiled fp32 GEMM: C[M x 256] = op(A)[M x K(lda)] * B[K x 256]
// BM=128, BN=64, BK=16, 256 threads, 8x4 microtile. Register prefetch of the
// next K-tile overlaps LDG latency with the FFMA block.
// FUSE: apply y = relu(a*scale[k] + shift[k]) to A elements while staging.
template <bool FUSE>
__global__ void __launch_bounds__(256) gemm_kernel(const float* __restrict__ A, int lda, int K,
                                                   const float* __restrict__ B,
                                                   float* __restrict__ C) {
    __shared__ float As[16][132];   // transposed stage, padded
    __shared__ float Bs[16][68];
    __shared__ float s_sc[ODIM];
    __shared__ float s_sh[ODIM];

    int tid = threadIdx.x;
    if (FUSE) {
        s_sc[tid] = g_scale[0][tid];
        s_sh[tid] = g_shift[0][tid];
    }
    int tx = tid & 15;              // col group (x4)
    int ty = tid >> 4;              // row group (x8)
    int mBase = blockIdx.y * 128;
    int nBase = blockIdx.x * 64;

    // A-stage geometry: 2 float4 per thread; B-stage: 1 float4
    int ar0 = tid >> 2;             // rows 0..63   (it=0) and +64 (it=1)
    int akq = (tid & 3) << 2;
    int bkr = tid >> 4;
    int bcq = (tid & 15) << 2;

    const float* Ab = A + (size_t)mBase * lda;
    const float* Bb = B + nBase;

    if (FUSE) __syncthreads();      // s_sc/s_sh ready before first STS phase

    float acc[8][4];
#pragma unroll
    for (int i = 0; i < 8; i++)
#pragma unroll
        for (int j = 0; j < 4; j++) acc[i][j] = 0.0f;

    // prologue: load tile 0 into registers
    float4 ra0 = *(const float4*)(Ab + (size_t)ar0 * lda + akq);
    float4 ra1 = *(const float4*)(Ab + (size_t)(ar0 + 64) * lda + akq);
    float4 rb  = *(const float4*)(Bb + (size_t)bkr * ODIM + bcq);

    for (int k0 = 0; k0 < K; k0 += 16) {
        // stage current tile regs -> smem (apply BN+ReLU on A if fusing)
        float4 v0 = ra0, v1 = ra1;
        if (FUSE) {
            v0.x = fmaxf(fmaf(v0.x, s_sc[k0 + akq + 0], s_sh[k0 + akq + 0]), 0.0f);
            v0.y = fmaxf(fmaf(v0.y, s_sc[k0 + akq + 1], s_sh[k0 + akq + 1]), 0.0f);
            v0.z = fmaxf(fmaf(v0.z, s_sc[k0 + akq + 2], s_sh[k0 + akq + 2]), 0.0f);
            v0.w = fmaxf(fmaf(v0.w, s_sc[k0 + akq + 3], s_sh[k0 + akq + 3]), 0.0f);
            v1.x = fmaxf(fmaf(v1.x, s_sc[k0 + akq + 0], s_sh[k0 + akq + 0]), 0.0f);
            v1.y = fmaxf(fmaf(v1.y, s_sc[k0 + akq + 1], s_sh[k0 + akq + 1]), 0.0f);
            v1.z = fmaxf(fmaf(v1.z, s_sc[k0 + akq + 2], s_sh[k0 + akq + 2]), 0.0f);
            v1.w = fmaxf(fmaf(v1.w, s_sc[k0 + akq + 3], s_sh[k0 + akq + 3]), 0.0f);
        }
        As[akq + 0][ar0] = v0.x;  As[akq + 1][ar0] = v0.y;
        As[akq + 2][ar0] = v0.z;  As[akq + 3][ar0] = v0.w;
        As[akq + 0][ar0 + 64] = v1.x;  As[akq + 1][ar0 + 64] = v1.y;
        As[akq + 2][ar0 + 64] = v1.z;  As[akq + 3][ar0 + 64] = v1.w;
        *(float4*)&Bs[bkr][bcq] = rb;
        __syncthreads();

        // prefetch next tile (LDG latency hides under compute below)
        if (k0 + 16 < K) {
            ra0 = *(const float4*)(Ab + (size_t)ar0 * lda + k0 + 16 + akq);
            ra1 = *(const float4*)(Ab + (size_t)(ar0 + 64) * lda + k0 + 16 + akq);
            rb  = *(const float4*)(Bb + (size_t)(k0 + 16 + bkr) * ODIM + bcq);
        }

#pragma unroll
        for (int kk = 0; kk < 16; kk++) {
            float a[8], b[4];
            *(float4*)(a + 0) = *(float4*)&As[kk][ty * 8 + 0];
            *(float4*)(a + 4) = *(float4*)&As[kk][ty * 8 + 4];
            *(float4*)(b)     = *(float4*)&Bs[kk][tx * 4];
#pragma unroll
            for (int i = 0; i < 8; i++)
#pragma unroll
                for (int j = 0; j < 4; j++)
                    acc[i][j] = fmaf(a[i], b[j], acc[i][j]);
        }
        __syncthreads();
    }
#pragma unroll
    for (int i = 0; i < 8; i++) {
        float4 v = make_float4(acc[i][0], acc[i][1], acc[i][2], acc[i][3]);
        *(float4*)(C + (size_t)(mBase + ty * 8 + i) * ODIM + nBase + tx * 4) = v;
    }
}

// ---------------- BN stats: per-channel sum / sumsq (deterministic 2-stage) ---
__global__ void __launch_bounds__(256) stats_kernel(const float* __restrict__ Y, int layer) {
    int c = threadIdx.x;
    int r0 = blockIdx.x * SROWS;
    float s = 0.0f, q = 0.0f;
    for (int r = 0; r < SROWS; r++) {
        float v = Y[(size_t)(r0 + r) * ODIM + c];
        s += v;
        q = fmaf(v, v, q);
    }
    g_part[layer][blockIdx.x][c] = s;
    g_part[layer][blockIdx.x][ODIM + c] = q;
}

// reduce partials + compute per-channel scale/shift
__global__ void __launch_bounds__(512) stats_reduce_kernel(int layer,
                                                           const float* __restrict__ gamma,
                                                           const float* __restrict__ beta) {
    __shared__ float ssum[2 * ODIM];
    int t = threadIdx.x;                      // 0..511
    float s = 0.0f;
    for (int r = 0; r < SBLK; r++) s += g_part[layer][r][t];
    ssum[t] = s;
    __syncthreads();
    if (t < ODIM) {
        float mu  = ssum[t] * INVN;
        float var = fmaf(-mu, mu, ssum[ODIM + t] * INVN);
        float sc = gamma[t] * rsqrtf(var + BN_EPS);
        g_scale[layer][t] = sc;
        g_shift[layer][t] = fmaf(-mu, sc, beta[t]);
    }
}

// ---------------- BN apply (final layer, no ReLU), float4 elementwise ---------
__global__ void __launch_bounds__(256) bn_apply_kernel(float* __restrict__ Y, int layer) {
    int idx = blockIdx.x * blockDim.x + threadIdx.x;   // one float4 each
    int e = idx * 4;
    int c = e & (ODIM - 1);
    float4 v = *(const float4*)(Y + e);
    float o[4] = {v.x, v.y, v.z, v.w};
#pragma unroll
    for (int j = 0; j < 4; j++) {
        int ch = c + j;
        o[j] = fmaf(o[j], g_scale[layer][ch], g_shift[layer][ch]);
    }
    *(float4*)(Y + e) = make_float4(o[0], o[1], o[2], o[3]);
}

// ---------------- launcher ----------------------------------------------------
extern "C" void kernel_launch(void* const* d_in, const int* in_sizes, int n_in,
                              void* d_out, int out_size) {
    const float* x   = (const float*)d_in[0];   // [8,2048,128]
    const float* pos = (const float*)d_in[1];   // [8,2048,3]
    const float* W1  = (const float*)d_in[2];   // [131,256]
    // d_in[3] = b1 (cancels under train-mode BN)
    const float* g1  = (const float*)d_in[4];
    const float* be1 = (const float*)d_in[5];
    const float* W2  = (const float*)d_in[6];   // [256,256]
    // d_in[7] = b2 (cancels)
    const float* g2  = (const float*)d_in[8];
    const float* be2 = (const float*)d_in[9];
    float* out = (float*)d_out;                 // [8,2048,256]

    prep_kernel<<<KPAD, ODIM>>>(W1);
    knn_kernel<<<BATCH * (NPTS / 64), 128>>>(pos);
    gather_avg_kernel<<<ROWS, 128>>>(x, pos);

    float* avg = nullptr; float* w1p = nullptr; float* c1 = nullptr;
    cudaGetSymbolAddress((void**)&avg, g_avg);
    cudaGetSymbolAddress((void**)&w1p, g_w1p);
    cudaGetSymbolAddress((void**)&c1,  g_c1);

    dim3 ggrid(ODIM / 64, ROWS / 128);
    gemm_kernel<false><<<ggrid, 256>>>(avg, KPAD, KPAD, w1p, c1);
    stats_kernel<<<SBLK, 256>>>(c1, 0);
    stats_reduce_kernel<<<1, 512>>>(0, g1, be1);

    // layer-2 GEMM with BN1+ReLU fused into A staging
    gemm_kernel<true><<<ggrid, 256>>>(c1, ODIM, ODIM, W2, out);
    stats_kernel<<<SBLK, 256>>>(out, 1);
    stats_reduce_kernel<<<1, 512>>>(1, g2, be2);
    bn_apply_kernel<<<ROWS * ODIM / 4 / 256, 256>>>(out, 1);
}

// round 6
// speedup vs baseline: 2.2906x; 1.0493x over previous
#include <cuda_runtime.h>
#include <cuda_bf16.h>
#include <math.h>

// Problem constants
#define BATCH 8
#define NPTS  2048
#define CDIM  128
#define PDIM  3
#define ODIM  256
#define KNN   16
#define ROWS  (BATCH * NPTS)       // 16384
#define KPAD  144                  // 131 padded up to multiple of 16
#define BN_EPS 1e-5f
#define INVN  (1.0f / (float)ROWS)
#define MBLK  (ROWS / 128)         // 128 m-blocks in gemm grid

typedef unsigned long long u64;

// ---------------- scratch (static device memory; no allocations) -------------
__device__ int   g_nn[ROWS * KNN];                 // 1 MB
__device__ float g_avg[ROWS * KPAD];               // 9.4 MB
__device__ float g_w1p[KPAD * ODIM];               // 147 KB (padded W1)
__device__ float g_c1[ROWS * ODIM];                // 16.8 MB (pre-BN layer1)
__device__ float g_partM[2][MBLK][2 * ODIM];       // gemm-epilogue partial sum|sumsq
__device__ float g_scale[2][ODIM];                 // BN scale per layer
__device__ float g_shift[2][ODIM];                 // BN shift per layer

// ---------------- prep: pad W1 ------------------------------------------------
__global__ void prep_kernel(const float* __restrict__ W1) {
    int k = blockIdx.x;          // 0..143
    int o = threadIdx.x;         // 0..255
    g_w1p[k * ODIM + o] = (k < 131) ? W1[k * ODIM + o] : 0.0f;
}

// ---------------- KNN --------------------------------------------------------
// 2 threads per query (even/odd point parity); register top-16 via deferred
// batched inserts; unique u64 keys (dist_bits<<32 | idx) = exact top_k
// semantics; pair-merge via shfl.
__device__ __forceinline__ u64 umax64(u64 a, u64 b) { return a > b ? a : b; }

__device__ __forceinline__ void insert16(u64 (&bk)[KNN], u64& wmax, u64 key) {
#pragma unroll
    for (int k = 0; k < KNN; k++) {
        if (bk[k] == wmax) bk[k] = key;      // unique keys: exactly one slot
    }
    u64 m0 = umax64(bk[0], bk[1]),   m1 = umax64(bk[2], bk[3]);
    u64 m2 = umax64(bk[4], bk[5]),   m3 = umax64(bk[6], bk[7]);
    u64 m4 = umax64(bk[8], bk[9]),   m5 = umax64(bk[10], bk[11]);
    u64 m6 = umax64(bk[12], bk[13]), m7 = umax64(bk[14], bk[15]);
    m0 = umax64(m0, m1); m2 = umax64(m2, m3);
    m4 = umax64(m4, m5); m6 = umax64(m6, m7);
    m0 = umax64(m0, m2); m4 = umax64(m4, m6);
    wmax = umax64(m0, m4);
}

__device__ __forceinline__ int warp_max_i(int v) {
    v = max(v, __shfl_xor_sync(0xFFFFFFFFu, v, 16));
    v = max(v, __shfl_xor_sync(0xFFFFFFFFu, v, 8));
    v = max(v, __shfl_xor_sync(0xFFFFFFFFu, v, 4));
    v = max(v, __shfl_xor_sync(0xFFFFFFFFu, v, 2));
    v = max(v, __shfl_xor_sync(0xFFFFFFFFu, v, 1));
    return v;
}

__global__ void __launch_bounds__(128) knn_kernel(const float* __restrict__ pos) {
    __shared__ float4 sp[NPTS];                    // 32 KB
    __shared__ u64 sbuf[16][128];                  // 16 KB, [slot][lane]
    int tid = threadIdx.x;
    int bb = blockIdx.x >> 5;                      // batch (32 blocks per batch)
    int r0 = (blockIdx.x & 31) << 6;               // query offset in batch (64/block)
    const float* pb = pos + bb * NPTS * PDIM;
    for (int j = tid; j < NPTS; j += 128) {
        sp[j] = make_float4(pb[j * 3 + 0], pb[j * 3 + 1], pb[j * 3 + 2], 0.0f);
    }
    __syncthreads();

    int qi = r0 + (tid >> 1);                      // query index (pairs share)
    int sub = tid & 1;                             // parity of points scanned
    float4 q = sp[qi];

    u64 bk[KNN];
#pragma unroll
    for (int k = 0; k < KNN; k++) bk[k] = 0xFFF0000000000000ull + (u64)k; // > any real key
    u64 wmax = 0xFFF000000000000Full;

    int n = 0;

    for (int j0 = 0; j0 < NPTS; j0 += 16) {
#pragma unroll
        for (int c = 0; c < 8; c++) {
            int j = j0 + 2 * c + sub;
            float4 p = sp[j];
            float dx = q.x - p.x, dy = q.y - p.y, dz = q.z - p.z;
            float d = dx * dx + dy * dy + dz * dz;
            u64 key = ((u64)__float_as_uint(d) << 32) | (unsigned)j;
            if (key < wmax) {                 // predicated push, no divergence
                sbuf[n][tid] = key;
                n++;
            }
        }
        if (__any_sync(0xFFFFFFFFu, n >= 8)) {
            int mx = warp_max_i(n);
            for (int k = 0; k < mx; k++) {    // lockstep rounds
                u64 key = sbuf[k][tid];
                if (k < n && key < wmax) {
                    insert16(bk, wmax, key);
                }
            }
            n = 0;
        }
    }
    {   // final flush
        int mx = warp_max_i(n);
        for (int k = 0; k < mx; k++) {
            u64 key = sbuf[k][tid];
            if (k < n && key < wmax) insert16(bk, wmax, key);
        }
    }

    // pair merge: even lane absorbs odd lane's 16 keys (union superset, exact)
#pragma unroll
    for (int k = 0; k < KNN; k++) {
        u64 pk = __shfl_xor_sync(0xFFFFFFFFu, bk[k], 1);
        if (sub == 0 && pk < wmax) insert16(bk, wmax, pk);
    }

    if (sub == 0) {
        int* o = g_nn + (bb * NPTS + qi) * KNN;
#pragma unroll
        for (int k = 0; k < KNN; k++) o[k] = (int)(bk[k] & 0xFFFFFFFFu);
    }
}

// ---------------- gather neighbors + mean -> avg[row][0..143] ----------------
__global__ void __launch_bounds__(128) gather_avg_kernel(const float* __restrict__ x,
                                                         const float* __restrict__ pos) {
    int row = blockIdx.x;                          // 0..16383
    int bb = row >> 11;
    __shared__ int sidx[KNN];
    if (threadIdx.x < KNN) sidx[threadIdx.x] = g_nn[row * KNN + threadIdx.x];
    __syncthreads();

    const float* xb = x + (size_t)bb * NPTS * CDIM;
    float s = 0.0f;
#pragma unroll
    for (int k = 0; k < KNN; k++) s += xb[sidx[k] * CDIM + threadIdx.x];
    g_avg[(size_t)row * KPAD + threadIdx.x] = s * (1.0f / (float)KNN);

    if (threadIdx.x < 16) {
        int c = threadIdx.x;
        float v = 0.0f;
        if (c < PDIM) {
            const float* pb = pos + bb * NPTS * PDIM;
#pragma unroll
            for (int k = 0; k < KNN; k++) v += pb[sidx[k] * PDIM + c];
            v *= (1.0f / (float)KNN);
        }
        g_avg[(size_t)row * KPAD + CDIM + c] = v;  // cols 128..130 pos-mean, rest 0
    }
}

// ---------------- tiled fp32 GEMM: C[M x 256] = op(A)[M x K(lda)] * B[K x 256]
// BM=128, BN=128, BK=16, 256 threads (16x16), 8x8 microtile: 64 FMA per
// 4 LDS.128 per kk (2x density of 8x4). Register prefetch of next K-tile.
// FUSE: BN1+ReLU applied to A while staging. Epilogue: deterministic
// per-channel partial sum/sumsq of the output tile -> g_partM[LAYER].
template <bool FUSE, int LAYER>
__global__ void __launch_bounds__(256) gemm_kernel(const float* __restrict__ A, int lda, int K,
                                                   const float* __restrict__ B,
                                                   float* __restrict__ C) {
    __shared__ float As[16][132];   // transposed A stage, padded
    __shared__ float Bs[16][132];   // B stage (uses first 128 cols)
    __shared__ float s_sc[ODIM];
    __shared__ float s_sh[ODIM];

    int tid = threadIdx.x;
    if (FUSE && tid < ODIM) {
        s_sc[tid] = g_scale[0][tid];
        s_sh[tid] = g_shift[0][tid];
    }
    int tx = tid & 15;              // col group (x8)
    int ty = tid >> 4;              // row group (x8)
    int mBase = blockIdx.y * 128;
    int nBase = blockIdx.x * 128;

    // A-stage: 2 float4/thread; B-stage: 2 float4/thread
    int ar0 = tid >> 2;             // rows 0..63 and +64
    int akq = (tid & 3) << 2;
    int bkr = tid >> 5;             // k-rows 0..7 and +8
    int bcq = (tid & 31) << 2;

    const float* Ab = A + (size_t)mBase * lda;
    const float* Bb = B + nBase;

    if (FUSE) __syncthreads();      // s_sc/s_sh ready before first staging

    float acc[8][8];
#pragma unroll
    for (int i = 0; i < 8; i++)
#pragma unroll
        for (int j = 0; j < 8; j++) acc[i][j] = 0.0f;

    // prologue: tile 0 into registers
    float4 ra0 = *(const float4*)(Ab + (size_t)ar0 * lda + akq);
    float4 ra1 = *(const float4*)(Ab + (size_t)(ar0 + 64) * lda + akq);
    float4 rb0 = *(const float4*)(Bb + (size_t)bkr * ODIM + bcq);
    float4 rb1 = *(const float4*)(Bb + (size_t)(bkr + 8) * ODIM + bcq);

    for (int k0 = 0; k0 < K; k0 += 16) {
        float4 v0 = ra0, v1 = ra1;
        if (FUSE) {
            v0.x = fmaxf(fmaf(v0.x, s_sc[k0 + akq + 0], s_sh[k0 + akq + 0]), 0.0f);
            v0.y = fmaxf(fmaf(v0.y, s_sc[k0 + akq + 1], s_sh[k0 + akq + 1]), 0.0f);
            v0.z = fmaxf(fmaf(v0.z, s_sc[k0 + akq + 2], s_sh[k0 + akq + 2]), 0.0f);
            v0.w = fmaxf(fmaf(v0.w, s_sc[k0 + akq + 3], s_sh[k0 + akq + 3]), 0.0f);
            v1.x = fmaxf(fmaf(v1.x, s_sc[k0 + akq + 0], s_sh[k0 + akq + 0]), 0.0f);
            v1.y = fmaxf(fmaf(v1.y, s_sc[k0 + akq + 1], s_sh[k0 + akq + 1]), 0.0f);
            v1.z = fmaxf(fmaf(v1.z, s_sc[k0 + akq + 2], s_sh[k0 + akq + 2]), 0.0f);
            v1.w = fmaxf(fmaf(v1.w, s_sc[k0 + akq + 3], s_sh[k0 + akq + 3]), 0.0f);
        }
        As[akq + 0][ar0] = v0.x;  As[akq + 1][ar0] = v0.y;
        As[akq + 2][ar0] = v0.z;  As[akq + 3][ar0] = v0.w;
        As[akq + 0][ar0 + 64] = v1.x;  As[akq + 1][ar0 + 64] = v1.y;
        As[akq + 2][ar0 + 64] = v1.z;  As[akq + 3][ar0 + 64] = v1.w;
        *(float4*)&Bs[bkr][bcq] = rb0;
        *(float4*)&Bs[bkr + 8][bcq] = rb1;
        __syncthreads();

        if (k0 + 16 < K) {          // prefetch next tile under the FMA block
            ra0 = *(const float4*)(Ab + (size_t)ar0 * lda + k0 + 16 + akq);
            ra1 = *(const float4*)(Ab + (size_t)(ar0 + 64) * lda + k0 + 16 + akq);
            rb0 = *(const float4*)(Bb + (size_t)(k0 + 16 + bkr) * ODIM + bcq);
            rb1 = *(const float4*)(Bb + (size_t)(k0 + 24 + bkr) * ODIM + bcq);
        }

#pragma unroll
        for (int kk = 0; kk < 16; kk++) {
            float a[8], b[8];
            *(float4*)(a + 0) = *(float4*)&As[kk][ty * 8 + 0];
            *(float4*)(a + 4) = *(float4*)&As[kk][ty * 8 + 4];
            *(float4*)(b + 0) = *(float4*)&Bs[kk][tx * 8 + 0];
            *(float4*)(b + 4) = *(float4*)&Bs[kk][tx * 8 + 4];
#pragma unroll
            for (int i = 0; i < 8; i++)
#pragma unroll
                for (int j = 0; j < 8; j++)
                    acc[i][j] = fmaf(a[i], b[j], acc[i][j]);
        }
        __syncthreads();
    }

    // write C
#pragma unroll
    for (int i = 0; i < 8; i++) {
        float* cr = C + (size_t)(mBase + ty * 8 + i) * ODIM + nBase + tx * 8;
        *(float4*)(cr + 0) = make_float4(acc[i][0], acc[i][1], acc[i][2], acc[i][3]);
        *(float4*)(cr + 4) = make_float4(acc[i][4], acc[i][5], acc[i][6], acc[i][7]);
    }

    // epilogue: deterministic per-channel partial sum / sumsq of this tile
    float (*tmpS)[132] = As;        // reuse stage buffers
    float (*tmpQ)[132] = Bs;
    float cs[8], cq[8];
#pragma unroll
    for (int j = 0; j < 8; j++) {
        float s = 0.0f, q = 0.0f;
#pragma unroll
        for (int i = 0; i < 8; i++) {
            s += acc[i][j];
            q = fmaf(acc[i][j], acc[i][j], q);
        }
        cs[j] = s; cq[j] = q;
    }
    __syncthreads();                // all LDS reads of As/Bs are done (post-loop sync passed)
#pragma unroll
    for (int j = 0; j < 8; j++) {
        tmpS[ty][tx * 8 + j] = cs[j];
        tmpQ[ty][tx * 8 + j] = cq[j];
    }
    __syncthreads();
    if (tid < 128) {
        float s = 0.0f, q = 0.0f;
#pragma unroll
        for (int t = 0; t < 16; t++) { s += tmpS[t][tid]; q += tmpQ[t][tid]; }
        g_partM[LAYER][blockIdx.y][nBase + tid] = s;
        g_partM[LAYER][blockIdx.y][ODIM + nBase + tid] = q;
    }
}

// reduce per-mblock partials + compute per-channel scale/shift
__global__ void __launch_bounds__(512) stats_reduce_kernel(int layer,
                                                           const float* __restrict__ gamma,
                                                           const float* __restrict__ beta) {
    __shared__ float ssum[2 * ODIM];
    int t = threadIdx.x;                      // 0..511
    float s = 0.0f;
    for (int r = 0; r < MBLK; r++) s += g_partM[layer][r][t];
    ssum[t] = s;
    __syncthreads();
    if (t < ODIM) {
        float mu  = ssum[t] * INVN;
        float var = fmaf(-mu, mu, ssum[ODIM + t] * INVN);
        float sc = gamma[t] * rsqrtf(var + BN_EPS);
        g_scale[layer][t] = sc;
        g_shift[layer][t] = fmaf(-mu, sc, beta[t]);
    }
}

// ---------------- BN apply (final layer, no ReLU), float4 elementwise ---------
__global__ void __launch_bounds__(256) bn_apply_kernel(float* __restrict__ Y, int layer) {
    int idx = blockIdx.x * blockDim.x + threadIdx.x;   // one float4 each
    int e = idx * 4;
    int c = e & (ODIM - 1);
    float4 v = *(const float4*)(Y + e);
    float o[4] = {v.x, v.y, v.z, v.w};
#pragma unroll
    for (int j = 0; j < 4; j++) {
        int ch = c + j;
        o[j] = fmaf(o[j], g_scale[layer][ch], g_shift[layer][ch]);
    }
    *(float4*)(Y + e) = make_float4(o[0], o[1], o[2], o[3]);
}

// ---------------- launcher ----------------------------------------------------
extern "C" void kernel_launch(void* const* d_in, const int* in_sizes, int n_in,
                              void* d_out, int out_size) {
    const float* x   = (const float*)d_in[0];   // [8,2048,128]
    const float* pos = (const float*)d_in[1];   // [8,2048,3]
    const float* W1  = (const float*)d_in[2];   // [131,256]
    // d_in[3] = b1 (cancels under train-mode BN)
    const float* g1  = (const float*)d_in[4];
    const float* be1 = (const float*)d_in[5];
    const float* W2  = (const float*)d_in[6];   // [256,256]
    // d_in[7] = b2 (cancels)
    const float* g2  = (const float*)d_in[8];
    const float* be2 = (const float*)d_in[9];
    float* out = (float*)d_out;                 // [8,2048,256]

    prep_kernel<<<KPAD, ODIM>>>(W1);
    knn_kernel<<<BATCH * (NPTS / 64), 128>>>(pos);
    gather_avg_kernel<<<ROWS, 128>>>(x, pos);

    float* avg = nullptr; float* w1p = nullptr; float* c1 = nullptr;
    cudaGetSymbolAddress((void**)&avg, g_avg);
    cudaGetSymbolAddress((void**)&w1p, g_w1p);
    cudaGetSymbolAddress((void**)&c1,  g_c1);

    dim3 ggrid(ODIM / 128, ROWS / 128);         // (2, 128)
    gemm_kernel<false, 0><<<ggrid, 256>>>(avg, KPAD, KPAD, w1p, c1);
    stats_reduce_kernel<<<1, 512>>>(0, g1, be1);

    // layer-2 GEMM with BN1+ReLU fused into A staging; stats fused in epilogue
    gemm_kernel<true, 1><<<ggrid, 256>>>(c1, ODIM, ODIM, W2, out);
    stats_reduce_kernel<<<1, 512>>>(1, g2, be2);
    bn_apply_kernel<<<ROWS * ODIM / 4 / 256, 256>>>(out, 1);
}

// round 7
// speedup vs baseline: 2.4811x; 1.0832x over previous
#include <cuda_runtime.h>
#include <cuda_bf16.h>
#include <math.h>
#include <stdint.h>

// Problem constants
#define BATCH 8
#define NPTS  2048
#define CDIM  128
#define PDIM  3
#define ODIM  256
#define KNN   16
#define ROWS  (BATCH * NPTS)       // 16384
#define KPAD  144                  // 131 padded up to multiple of 16
#define BN_EPS 1e-5f
#define INVN  (1.0f / (float)ROWS)
#define MBLK  (ROWS / 128)         // 128 m-blocks in gemm grid

typedef unsigned long long u64;

// ---------------- scratch (static device memory; no allocations) -------------
__device__ int   g_nn[ROWS * KNN];                 // 1 MB
__device__ float g_avg[ROWS * KPAD];               // 9.4 MB
__device__ float g_w1p[KPAD * ODIM];               // 147 KB (padded W1)
__device__ float g_c1[ROWS * ODIM];                // 16.8 MB (pre-BN layer1)
__device__ float g_partM[2][MBLK][2 * ODIM];       // gemm-epilogue partial sum|sumsq
__device__ float g_scale[2][ODIM];                 // BN scale per layer
__device__ float g_shift[2][ODIM];                 // BN shift per layer

// ---------------- prep: pad W1 ------------------------------------------------
__global__ void prep_kernel(const float* __restrict__ W1) {
    int k = blockIdx.x;          // 0..143
    int o = threadIdx.x;         // 0..255
    g_w1p[k * ODIM + o] = (k < 131) ? W1[k * ODIM + o] : 0.0f;
}

// ---------------- KNN (unchanged from round 6) -------------------------------
__device__ __forceinline__ u64 umax64(u64 a, u64 b) { return a > b ? a : b; }

__device__ __forceinline__ void insert16(u64 (&bk)[KNN], u64& wmax, u64 key) {
#pragma unroll
    for (int k = 0; k < KNN; k++) {
        if (bk[k] == wmax) bk[k] = key;      // unique keys: exactly one slot
    }
    u64 m0 = umax64(bk[0], bk[1]),   m1 = umax64(bk[2], bk[3]);
    u64 m2 = umax64(bk[4], bk[5]),   m3 = umax64(bk[6], bk[7]);
    u64 m4 = umax64(bk[8], bk[9]),   m5 = umax64(bk[10], bk[11]);
    u64 m6 = umax64(bk[12], bk[13]), m7 = umax64(bk[14], bk[15]);
    m0 = umax64(m0, m1); m2 = umax64(m2, m3);
    m4 = umax64(m4, m5); m6 = umax64(m6, m7);
    m0 = umax64(m0, m2); m4 = umax64(m4, m6);
    wmax = umax64(m0, m4);
}

__device__ __forceinline__ int warp_max_i(int v) {
    v = max(v, __shfl_xor_sync(0xFFFFFFFFu, v, 16));
    v = max(v, __shfl_xor_sync(0xFFFFFFFFu, v, 8));
    v = max(v, __shfl_xor_sync(0xFFFFFFFFu, v, 4));
    v = max(v, __shfl_xor_sync(0xFFFFFFFFu, v, 2));
    v = max(v, __shfl_xor_sync(0xFFFFFFFFu, v, 1));
    return v;
}

__global__ void __launch_bounds__(128) knn_kernel(const float* __restrict__ pos) {
    __shared__ float4 sp[NPTS];                    // 32 KB
    __shared__ u64 sbuf[16][128];                  // 16 KB, [slot][lane]
    int tid = threadIdx.x;
    int bb = blockIdx.x >> 5;
    int r0 = (blockIdx.x & 31) << 6;
    const float* pb = pos + bb * NPTS * PDIM;
    for (int j = tid; j < NPTS; j += 128) {
        sp[j] = make_float4(pb[j * 3 + 0], pb[j * 3 + 1], pb[j * 3 + 2], 0.0f);
    }
    __syncthreads();

    int qi = r0 + (tid >> 1);
    int sub = tid & 1;
    float4 q = sp[qi];

    u64 bk[KNN];
#pragma unroll
    for (int k = 0; k < KNN; k++) bk[k] = 0xFFF0000000000000ull + (u64)k;
    u64 wmax = 0xFFF000000000000Full;

    int n = 0;
    for (int j0 = 0; j0 < NPTS; j0 += 16) {
#pragma unroll
        for (int c = 0; c < 8; c++) {
            int j = j0 + 2 * c + sub;
            float4 p = sp[j];
            float dx = q.x - p.x, dy = q.y - p.y, dz = q.z - p.z;
            float d = dx * dx + dy * dy + dz * dz;
            u64 key = ((u64)__float_as_uint(d) << 32) | (unsigned)j;
            if (key < wmax) { sbuf[n][tid] = key; n++; }
        }
        if (__any_sync(0xFFFFFFFFu, n >= 8)) {
            int mx = warp_max_i(n);
            for (int k = 0; k < mx; k++) {
                u64 key = sbuf[k][tid];
                if (k < n && key < wmax) insert16(bk, wmax, key);
            }
            n = 0;
        }
    }
    {
        int mx = warp_max_i(n);
        for (int k = 0; k < mx; k++) {
            u64 key = sbuf[k][tid];
            if (k < n && key < wmax) insert16(bk, wmax, key);
        }
    }
#pragma unroll
    for (int k = 0; k < KNN; k++) {
        u64 pk = __shfl_xor_sync(0xFFFFFFFFu, bk[k], 1);
        if (sub == 0 && pk < wmax) insert16(bk, wmax, pk);
    }
    if (sub == 0) {
        int* o = g_nn + (bb * NPTS + qi) * KNN;
#pragma unroll
        for (int k = 0; k < KNN; k++) o[k] = (int)(bk[k] & 0xFFFFFFFFu);
    }
}

// ---------------- gather neighbors + mean -> avg[row][0..143] ----------------
__global__ void __launch_bounds__(128) gather_avg_kernel(const float* __restrict__ x,
                                                         const float* __restrict__ pos) {
    int row = blockIdx.x;
    int bb = row >> 11;
    __shared__ int sidx[KNN];
    if (threadIdx.x < KNN) sidx[threadIdx.x] = g_nn[row * KNN + threadIdx.x];
    __syncthreads();

    const float* xb = x + (size_t)bb * NPTS * CDIM;
    float s = 0.0f;
#pragma unroll
    for (int k = 0; k < KNN; k++) s += xb[sidx[k] * CDIM + threadIdx.x];
    g_avg[(size_t)row * KPAD + threadIdx.x] = s * (1.0f / (float)KNN);

    if (threadIdx.x < 16) {
        int c = threadIdx.x;
        float v = 0.0f;
        if (c < PDIM) {
            const float* pb = pos + bb * NPTS * PDIM;
#pragma unroll
            for (int k = 0; k < KNN; k++) v += pb[sidx[k] * PDIM + c];
            v *= (1.0f / (float)KNN);
        }
        g_avg[(size_t)row * KPAD + CDIM + c] = v;
    }
}

// ---------------- 3xTF32 tensor-core GEMM ------------------------------------
// C[M x 256] = op(A)[M x K] * B[K x 256], exact-to-~1e-6 via Dekker split:
// x = hi + lo (hi = tf32_rna(x), lo = tf32_rna(x - hi));  x*y ~= Ah*Bh + Ah*Bl + Al*Bh.
// BM=128, BN=128, BK=16, 256 thr = 8 warps (2m x 4n), warp tile 64x32
// (4x4 m16n8k8 tiles, fp32 acc). hi/lo split once at staging; smem row pad 136
// makes all fragment gathers bank-conflict-free. FUSE: BN1+ReLU on A staging.
// Epilogue: deterministic per-channel sum/sumsq from acc frags via shfl.
__device__ __forceinline__ uint32_t f2tf32(float x) {
    uint32_t r;
    asm("cvt.rna.tf32.f32 %0, %1;" : "=r"(r) : "f"(x));
    return r;
}
__device__ __forceinline__ void tf32_split(float x, float& hi, float& lo) {
    uint32_t h = f2tf32(x);
    hi = __uint_as_float(h);
    lo = __uint_as_float(f2tf32(x - hi));
}
__device__ __forceinline__ void mma_tf32(float* c, uint32_t a0, uint32_t a1,
                                         uint32_t a2, uint32_t a3,
                                         uint32_t b0, uint32_t b1) {
    asm volatile(
        "mma.sync.aligned.m16n8k8.row.col.f32.tf32.tf32.f32 "
        "{%0,%1,%2,%3}, {%4,%5,%6,%7}, {%8,%9}, {%0,%1,%2,%3};\n"
        : "+f"(c[0]), "+f"(c[1]), "+f"(c[2]), "+f"(c[3])
        : "r"(a0), "r"(a1), "r"(a2), "r"(a3), "r"(b0), "r"(b1));
}

template <bool FUSE, int LAYER>
__global__ void __launch_bounds__(256, 2) gemm_tc(const float* __restrict__ A, int lda, int K,
                                                  const float* __restrict__ B,
                                                  float* __restrict__ C) {
    __shared__ float Ah[16][136], Al[16][136];     // A stage transposed [k][m]
    __shared__ float Bh[16][136], Bl[16][136];     // B stage [k][n]
    __shared__ float s_sc[ODIM], s_sh[ODIM];
    __shared__ float sS[2][128], sQ[2][128];

    int tid = threadIdx.x;
    if (FUSE) { s_sc[tid] = g_scale[0][tid]; s_sh[tid] = g_shift[0][tid]; }

    int wid = tid >> 5;
    int lane = tid & 31;
    int gid = lane >> 2;            // group id 0..7
    int tig = lane & 3;             // thread-in-group 0..3
    int wm = wid >> 2;              // 0..1 -> 64-row half
    int wn = wid & 3;               // 0..3 -> 32-col slice
    int mBase = blockIdx.y * 128;
    int nBase = blockIdx.x * 128;

    // staging geometry
    int ar0 = tid >> 2;             // A rows 0..63 (+64)
    int akq = (tid & 3) << 2;       // A k-offset
    int bkr = tid >> 5;             // B k-rows 0..7 (+8)
    int bcq = (tid & 31) << 2;      // B n-offset

    const float* Ab = A + (size_t)mBase * lda;
    const float* Bb = B + nBase;

    if (FUSE) __syncthreads();

    float acc[4][4][4];
#pragma unroll
    for (int mt = 0; mt < 4; mt++)
#pragma unroll
        for (int nt = 0; nt < 4; nt++)
#pragma unroll
            for (int e = 0; e < 4; e++) acc[mt][nt][e] = 0.0f;

    // prologue: tile 0
    float4 ra0 = *(const float4*)(Ab + (size_t)ar0 * lda + akq);
    float4 ra1 = *(const float4*)(Ab + (size_t)(ar0 + 64) * lda + akq);
    float4 rb0 = *(const float4*)(Bb + (size_t)bkr * ODIM + bcq);
    float4 rb1 = *(const float4*)(Bb + (size_t)(bkr + 8) * ODIM + bcq);

    for (int k0 = 0; k0 < K; k0 += 16) {
        // ---- stage with hi/lo split (FUSE: BN+ReLU first) ----
        float av0[4] = {ra0.x, ra0.y, ra0.z, ra0.w};
        float av1[4] = {ra1.x, ra1.y, ra1.z, ra1.w};
        if (FUSE) {
#pragma unroll
            for (int i = 0; i < 4; i++) {
                float sc = s_sc[k0 + akq + i], sh = s_sh[k0 + akq + i];
                av0[i] = fmaxf(fmaf(av0[i], sc, sh), 0.0f);
                av1[i] = fmaxf(fmaf(av1[i], sc, sh), 0.0f);
            }
        }
#pragma unroll
        for (int i = 0; i < 4; i++) {
            float h, l;
            tf32_split(av0[i], h, l);
            Ah[akq + i][ar0] = h;  Al[akq + i][ar0] = l;
            tf32_split(av1[i], h, l);
            Ah[akq + i][ar0 + 64] = h;  Al[akq + i][ar0 + 64] = l;
        }
        {
            float bv0[4] = {rb0.x, rb0.y, rb0.z, rb0.w};
            float bv1[4] = {rb1.x, rb1.y, rb1.z, rb1.w};
            float4 h0, l0, h1, l1;
            tf32_split(bv0[0], h0.x, l0.x); tf32_split(bv0[1], h0.y, l0.y);
            tf32_split(bv0[2], h0.z, l0.z); tf32_split(bv0[3], h0.w, l0.w);
            tf32_split(bv1[0], h1.x, l1.x); tf32_split(bv1[1], h1.y, l1.y);
            tf32_split(bv1[2], h1.z, l1.z); tf32_split(bv1[3], h1.w, l1.w);
            *(float4*)&Bh[bkr][bcq] = h0;  *(float4*)&Bl[bkr][bcq] = l0;
            *(float4*)&Bh[bkr + 8][bcq] = h1;  *(float4*)&Bl[bkr + 8][bcq] = l1;
        }
        __syncthreads();

        if (k0 + 16 < K) {          // prefetch next tile under the MMA block
            ra0 = *(const float4*)(Ab + (size_t)ar0 * lda + k0 + 16 + akq);
            ra1 = *(const float4*)(Ab + (size_t)(ar0 + 64) * lda + k0 + 16 + akq);
            rb0 = *(const float4*)(Bb + (size_t)(k0 + 16 + bkr) * ODIM + bcq);
            rb1 = *(const float4*)(Bb + (size_t)(k0 + 24 + bkr) * ODIM + bcq);
        }

        // ---- compute: 2 k8 steps ----
#pragma unroll
        for (int g = 0; g < 2; g++) {
            int kr0 = g * 8 + tig;
            int kr1 = kr0 + 4;
            uint32_t bh[4][2], bl[4][2];
#pragma unroll
            for (int nt = 0; nt < 4; nt++) {
                int n = wn * 32 + nt * 8 + gid;
                bh[nt][0] = __float_as_uint(Bh[kr0][n]);
                bh[nt][1] = __float_as_uint(Bh[kr1][n]);
                bl[nt][0] = __float_as_uint(Bl[kr0][n]);
                bl[nt][1] = __float_as_uint(Bl[kr1][n]);
            }
#pragma unroll
            for (int mt = 0; mt < 4; mt++) {
                int m = wm * 64 + mt * 16 + gid;
                uint32_t ah0 = __float_as_uint(Ah[kr0][m]);
                uint32_t ah1 = __float_as_uint(Ah[kr0][m + 8]);
                uint32_t ah2 = __float_as_uint(Ah[kr1][m]);
                uint32_t ah3 = __float_as_uint(Ah[kr1][m + 8]);
                uint32_t al0 = __float_as_uint(Al[kr0][m]);
                uint32_t al1 = __float_as_uint(Al[kr0][m + 8]);
                uint32_t al2 = __float_as_uint(Al[kr1][m]);
                uint32_t al3 = __float_as_uint(Al[kr1][m + 8]);
#pragma unroll
                for (int nt = 0; nt < 4; nt++) {
                    mma_tf32(acc[mt][nt], ah0, ah1, ah2, ah3, bh[nt][0], bh[nt][1]);
                    mma_tf32(acc[mt][nt], ah0, ah1, ah2, ah3, bl[nt][0], bl[nt][1]);
                    mma_tf32(acc[mt][nt], al0, al1, al2, al3, bh[nt][0], bh[nt][1]);
                }
            }
        }
        __syncthreads();
    }

    // ---- write C (float2 per fragment row) ----
#pragma unroll
    for (int mt = 0; mt < 4; mt++) {
#pragma unroll
        for (int nt = 0; nt < 4; nt++) {
            int r = mBase + wm * 64 + mt * 16 + gid;
            int cc = nBase + wn * 32 + nt * 8 + 2 * tig;
            *(float2*)(C + (size_t)r * ODIM + cc) = make_float2(acc[mt][nt][0], acc[mt][nt][1]);
            *(float2*)(C + (size_t)(r + 8) * ODIM + cc) = make_float2(acc[mt][nt][2], acc[mt][nt][3]);
        }
    }

    // ---- epilogue: deterministic per-channel partial sum / sumsq ----
    float cs[4][2], cq[4][2];
#pragma unroll
    for (int nt = 0; nt < 4; nt++) {
#pragma unroll
        for (int e = 0; e < 2; e++) {
            float s = 0.0f, q = 0.0f;
#pragma unroll
            for (int mt = 0; mt < 4; mt++) {
                float v0 = acc[mt][nt][e], v1 = acc[mt][nt][e + 2];
                s += v0 + v1;
                q = fmaf(v0, v0, q);
                q = fmaf(v1, v1, q);
            }
            cs[nt][e] = s; cq[nt][e] = q;
        }
    }
#pragma unroll
    for (int nt = 0; nt < 4; nt++) {
#pragma unroll
        for (int e = 0; e < 2; e++) {
            float s = cs[nt][e], q = cq[nt][e];
            s += __shfl_xor_sync(0xFFFFFFFFu, s, 4);
            s += __shfl_xor_sync(0xFFFFFFFFu, s, 8);
            s += __shfl_xor_sync(0xFFFFFFFFu, s, 16);
            q += __shfl_xor_sync(0xFFFFFFFFu, q, 4);
            q += __shfl_xor_sync(0xFFFFFFFFu, q, 8);
            q += __shfl_xor_sync(0xFFFFFFFFu, q, 16);
            if (gid == 0) {
                int c = wn * 32 + nt * 8 + 2 * tig + e;
                sS[wm][c] = s;  sQ[wm][c] = q;
            }
        }
    }
    __syncthreads();
    if (tid < 128) {
        float s = sS[0][tid] + sS[1][tid];
        float q = sQ[0][tid] + sQ[1][tid];
        g_partM[LAYER][blockIdx.y][nBase + tid] = s;
        g_partM[LAYER][blockIdx.y][ODIM + nBase + tid] = q;
    }
}

// reduce per-mblock partials + compute per-channel scale/shift
__global__ void __launch_bounds__(512) stats_reduce_kernel(int layer,
                                                           const float* __restrict__ gamma,
                                                           const float* __restrict__ beta) {
    __shared__ float ssum[2 * ODIM];
    int t = threadIdx.x;
    float s = 0.0f;
    for (int r = 0; r < MBLK; r++) s += g_partM[layer][r][t];
    ssum[t] = s;
    __syncthreads();
    if (t < ODIM) {
        float mu  = ssum[t] * INVN;
        float var = fmaf(-mu, mu, ssum[ODIM + t] * INVN);
        float sc = gamma[t] * rsqrtf(var + BN_EPS);
        g_scale[layer][t] = sc;
        g_shift[layer][t] = fmaf(-mu, sc, beta[t]);
    }
}

// ---------------- BN apply (final layer, no ReLU), float4 elementwise ---------
__global__ void __launch_bounds__(256) bn_apply_kernel(float* __restrict__ Y, int layer) {
    int idx = blockIdx.x * blockDim.x + threadIdx.x;
    int e = idx * 4;
    int c = e & (ODIM - 1);
    float4 v = *(const float4*)(Y + e);
    float o[4] = {v.x, v.y, v.z, v.w};
#pragma unroll
    for (int j = 0; j < 4; j++) {
        int ch = c + j;
        o[j] = fmaf(o[j], g_scale[layer][ch], g_shift[layer][ch]);
    }
    *(float4*)(Y + e) = make_float4(o[0], o[1], o[2], o[3]);
}

// ---------------- launcher ----------------------------------------------------
extern "C" void kernel_launch(void* const* d_in, const int* in_sizes, int n_in,
                              void* d_out, int out_size) {
    const float* x   = (const float*)d_in[0];   // [8,2048,128]
    const float* pos = (const float*)d_in[1];   // [8,2048,3]
    const float* W1  = (const float*)d_in[2];   // [131,256]
    // d_in[3] = b1 (cancels under train-mode BN)
    const float* g1  = (const float*)d_in[4];
    const float* be1 = (const float*)d_in[5];
    const float* W2  = (const float*)d_in[6];   // [256,256]
    // d_in[7] = b2 (cancels)
    const float* g2  = (const float*)d_in[8];
    const float* be2 = (const float*)d_in[9];
    float* out = (float*)d_out;                 // [8,2048,256]

    prep_kernel<<<KPAD, ODIM>>>(W1);
    knn_kernel<<<BATCH * (NPTS / 64), 128>>>(pos);
    gather_avg_kernel<<<ROWS, 128>>>(x, pos);

    float* avg = nullptr; float* w1p = nullptr; float* c1 = nullptr;
    cudaGetSymbolAddress((void**)&avg, g_avg);
    cudaGetSymbolAddress((void**)&w1p, g_w1p);
    cudaGetSymbolAddress((void**)&c1,  g_c1);

    dim3 ggrid(ODIM / 128, ROWS / 128);         // (2, 128)
    gemm_tc<false, 0><<<ggrid, 256>>>(avg, KPAD, KPAD, w1p, c1);
    stats_reduce_kernel<<<1, 512>>>(0, g1, be1);

    // layer-2 GEMM with BN1+ReLU fused into A staging; stats fused in epilogue
    gemm_tc<true, 1><<<ggrid, 256>>>(c1, ODIM, ODIM, W2, out);
    stats_reduce_kernel<<<1, 512>>>(1, g2, be2);
    bn_apply_kernel<<<ROWS * ODIM / 4 / 256, 256>>>(out, 1);
}